// round 15
// baseline (speedup 1.0000x reference)
#include <cuda_runtime.h>
#include <cstdint>

#define D_MODEL 1024
#define NHEAD   16
#define DHEAD   64
#define BATCH   4
#define SEQ     2048
#define ROWS    (BATCH * SEQ)          // 8192
#define QKV_N   (3 * D_MODEL)          // 3072
#define KDIM    1024

// Scratch (allocation-free rule: __device__ globals)
__device__ float g_Q[BATCH * NHEAD * SEQ * DHEAD];   // [B,H,L,Dh]
__device__ float g_K[BATCH * NHEAD * SEQ * DHEAD];
__device__ float g_V[BATCH * NHEAD * SEQ * DHEAD];
__device__ float g_ctx[ROWS * D_MODEL];              // [B,L,H*Dh] (tf32-rounded)
__device__ float g_Xt[ROWS * KDIM];                  // x, tf32(rna)
__device__ float g_Wq[KDIM * QKV_N];                 // w_qkv, tf32(rna)
__device__ float g_Wo[KDIM * D_MODEL];               // w_out, tf32(rna)

// ---------------------------------------------------------------------------
// helpers
// ---------------------------------------------------------------------------
__device__ __forceinline__ float f2tf32(float x) {
    uint32_t b;
    asm("cvt.rna.tf32.f32 %0, %1;" : "=r"(b) : "f"(x));
    return __uint_as_float(b);
}

// D += A*B, m16n8k8 tf32
__device__ __forceinline__ void mma_tf32(float* d, const uint32_t* a, const uint32_t* b) {
    asm volatile(
        "mma.sync.aligned.m16n8k8.row.col.f32.tf32.tf32.f32 "
        "{%0,%1,%2,%3}, {%4,%5,%6,%7}, {%8,%9}, {%0,%1,%2,%3};"
        : "+f"(d[0]), "+f"(d[1]), "+f"(d[2]), "+f"(d[3])
        : "r"(a[0]), "r"(a[1]), "r"(a[2]), "r"(a[3]), "r"(b[0]), "r"(b[1]));
}

__device__ __forceinline__ uint32_t smem_u32(const void* p) {
    uint32_t a;
    asm("{ .reg .u64 t; cvta.to.shared.u64 t, %1; cvt.u32.u64 %0, t; }"
        : "=r"(a) : "l"(p));
    return a;
}

// ldmatrix x4 (tf32 bits via the b16 path): lane L of tile t gets the
// 4-byte element L%4 of the 16B row addressed by lane (8t + L/4).
__device__ __forceinline__ void ldsm_x4(uint32_t* r, uint32_t addr) {
    asm volatile("ldmatrix.sync.aligned.m8n8.x4.shared.b16 {%0,%1,%2,%3}, [%4];"
                 : "=r"(r[0]), "=r"(r[1]), "=r"(r[2]), "=r"(r[3]) : "r"(addr));
}

__device__ __forceinline__ void cp16(uint32_t dst, const void* src) {
    asm volatile("cp.async.cg.shared.global [%0], [%1], 16;"
                 :: "r"(dst), "l"(src) : "memory");
}
#define CP_COMMIT() asm volatile("cp.async.commit_group;" ::: "memory")
#define CP_WAIT(n)  asm volatile("cp.async.wait_group %0;" :: "n"(n) : "memory")

// ---------------------------------------------------------------------------
// tf32(rna) pre-conversion
// ---------------------------------------------------------------------------
__global__ __launch_bounds__(256) void conv_tf32(
    const float* __restrict__ src, float* __restrict__ dst)
{
    int i = blockIdx.x * 256 + threadIdx.x;
    float4 v = ((const float4*)src)[i];
    v.x = f2tf32(v.x); v.y = f2tf32(v.y);
    v.z = f2tf32(v.z); v.w = f2tf32(v.w);
    ((float4*)dst)[i] = v;
}

// ---------------------------------------------------------------------------
// mma.sync tf32 GEMM: C[M,N] = A[M,1024] @ W[1024,N] + bias
// A fragments via ldmatrix.x4 on the XOR-swizzled A stage; B scalar LDS.
// ---------------------------------------------------------------------------
#define GBM 128
#define GBN 128
#define GBK 32
#define NKIT (KDIM / GBK)        // 32
#define ASTG 4096                // floats: 128*32
#define BSTG 4352                // floats: 32*136
#define STG  (ASTG + BSTG)       // 8448 floats = 33792 B
#define NSTAGE 3
#define GEMM_SMEM (NSTAGE * STG * 4)   // 101376 B

template<int QKV>
__global__ __launch_bounds__(256) void tc_gemm(
    const float* __restrict__ A, const float* __restrict__ W,
    const float* __restrict__ bias, float* __restrict__ out, int ldn)
{
    extern __shared__ float sm[];

    const int tid  = threadIdx.x;
    const int lane = tid & 31;
    const int warp = tid >> 5;
    const int wm   = warp >> 2;     // 0..1
    const int wn   = warp & 3;      // 0..3
    const int g    = lane >> 2;     // 0..7
    const int t4   = lane & 3;      // 0..3
    const int l7   = lane & 7;
    const int lh   = (lane >> 3) & 1;
    const int lq   = lane >> 4;

    const int bn = blockIdx.x * GBN;
    const int bm = blockIdx.y * GBM;

    float d[4][4][4];
    #pragma unroll
    for (int i = 0; i < 4; i++)
        #pragma unroll
        for (int j = 0; j < 4; j++)
            #pragma unroll
            for (int r = 0; r < 4; r++) d[i][j][r] = 0.f;

    const uint32_t smb = smem_u32(sm);

    auto stage = [&](int c, int buf) {
        uint32_t ab = smb + (uint32_t)buf * (STG * 4);
        uint32_t bb = ab + ASTG * 4;
        #pragma unroll
        for (int i = 0; i < 4; i++) {
            int j = tid + 256 * i;
            int m = j >> 3, kc4 = j & 7;
            cp16(ab + (uint32_t)(m * 32 + ((kc4 ^ (m & 7)) << 2)) * 4,
                 A + (size_t)(bm + m) * KDIM + c * GBK + kc4 * 4);
        }
        #pragma unroll
        for (int i = 0; i < 4; i++) {
            int j = tid + 256 * i;
            int k = j >> 5, nc4 = j & 31;
            cp16(bb + (uint32_t)(k * 136 + nc4 * 4) * 4,
                 W + (size_t)(c * GBK + k) * ldn + bn + nc4 * 4);
        }
    };

    stage(0, 0); CP_COMMIT();
    stage(1, 1); CP_COMMIT();

    // per-lane A ldsm address pieces:
    //   a0: rows-lo k-lo (lanes 0-7), a1: rows-hi k-lo (8-15),
    //   a2: rows-lo k-hi (16-23),     a3: rows-hi k-hi (24-31)
    // addr(tm,tk) = Abuf + (wm*64 + tm*16 + l7 + 8*lh)*128 + 16*((2tk+lq)^l7)
    const uint32_t aRowOff = (uint32_t)((wm * 64 + l7 + 8 * lh) * 128);

    int buf = 0;
    for (int c = 0; c < NKIT; c++) {
        CP_WAIT(1);
        __syncthreads();

        const uint32_t AbA = smb + (uint32_t)buf * (STG * 4) + aRowOff;
        const float* Bb = sm + buf * STG + ASTG;

        #pragma unroll
        for (int tk = 0; tk < 4; tk++) {
            uint32_t af[4][4], bf[4][2];
            const uint32_t xorv = (uint32_t)(((2 * tk + lq) ^ l7) << 4);
            #pragma unroll
            for (int tm = 0; tm < 4; tm++)
                ldsm_x4(af[tm], AbA + (uint32_t)(tm * 16 * 128) + xorv);
            #pragma unroll
            for (int tn = 0; tn < 4; tn++) {
                int n = wn * 32 + tn * 8 + g;
                bf[tn][0] = __float_as_uint(Bb[(8 * tk + t4) * 136 + n]);
                bf[tn][1] = __float_as_uint(Bb[(8 * tk + t4 + 4) * 136 + n]);
            }
            #pragma unroll
            for (int tm = 0; tm < 4; tm++)
                #pragma unroll
                for (int tn = 0; tn < 4; tn++)
                    mma_tf32(d[tm][tn], af[tm], bf[tn]);
        }

        __syncthreads();
        if (c + 2 < NKIT) stage(c + 2, (buf + 2) % NSTAGE);
        CP_COMMIT();

        buf = (buf + 1) % NSTAGE;
    }

    // ---- epilogue ----
    const int bb2 = bm >> 11;
    #pragma unroll
    for (int tm = 0; tm < 4; tm++) {
        int m0 = bm + wm * 64 + tm * 16 + g;
        #pragma unroll
        for (int tn = 0; tn < 4; tn++) {
            int n0 = bn + wn * 32 + tn * 8 + t4 * 2;
            float bx = __ldg(&bias[n0]);
            float by = __ldg(&bias[n0 + 1]);
            float v0 = d[tm][tn][0] + bx, v1 = d[tm][tn][1] + by;
            float v2 = d[tm][tn][2] + bx, v3 = d[tm][tn][3] + by;
            if (QKV) {
                int s = n0 >> 10, h = (n0 & 1023) >> 6, d0 = n0 & 63;
                int ll = m0 & (SEQ - 1);
                float* base = (s == 0 ? g_Q : (s == 1 ? g_K : g_V))
                              + ((size_t)(bb2 * NHEAD + h) * SEQ) * DHEAD + d0;
                *(float2*)(base + (size_t)ll * DHEAD)       = make_float2(v0, v1);
                *(float2*)(base + (size_t)(ll + 8) * DHEAD) = make_float2(v2, v3);
            } else {
                *(float2*)(out + (size_t)m0 * D_MODEL + n0)       = make_float2(v0, v1);
                *(float2*)(out + (size_t)(m0 + 8) * D_MODEL + n0) = make_float2(v2, v3);
            }
        }
    }
}

// ---------------------------------------------------------------------------
// Tensor-core flash attention (mma.sync tf32).
// K fragments via ldmatrix.x4 (row stride 272B = 16B-aligned, phases
// conflict-free). P conversion via per-warp smem [16][76] (STS.64 +
// ldmatrix.x4) instead of the 64-shuffle chain. V fragments scalar.
// ---------------------------------------------------------------------------
#define ATT_KT   64
#define K_STRIDE 68
#define V_STRIDE 72
#define P_STRIDE 76
#define KB_BYTES (64 * K_STRIDE * 4)   // 17408
#define VB_BYTES (64 * V_STRIDE * 4)   // 18432
#define PSM_FLOATS (16 * P_STRIDE)     // 1216 floats = 4864 B per warp
#define ATT_P_OFF (2 * (KB_BYTES + VB_BYTES))          // 71680
#define ATT_SMEM (ATT_P_OFF + 4 * PSM_FLOATS * 4)      // 91136

__global__ __launch_bounds__(128) void attn_mma_kernel()
{
    extern __shared__ float asm_[];

    const int tid  = threadIdx.x;
    const int lane = tid & 31;
    const int wid  = tid >> 5;
    const int g    = lane >> 2;
    const int t4   = lane & 3;
    const int l7   = lane & 7;
    const int lh   = (lane >> 3) & 1;
    const int lq   = lane >> 4;

    const int b  = blockIdx.z;
    const int h  = blockIdx.y;
    const int q0 = blockIdx.x * 64;

    const size_t head_off = ((size_t)(b * NHEAD) + h) * SEQ * DHEAD;
    const float* __restrict__ Qb = g_Q + head_off;
    const float* __restrict__ Kb = g_K + head_off;
    const float* __restrict__ Vb = g_V + head_off;

    const uint32_t smb = smem_u32(asm_);

    // K ldsm lane offset: x4 covers j-tiles {2j2, 2j2+1}:
    //   lanes 0-7: row 16j2+l7, chunk-lo; 8-15: chunk-hi; 16-31: rows +8..
    const uint32_t kLane = (uint32_t)((8 * lq + l7) * (K_STRIDE * 4) + lh * 16);
    // P ldsm lane offset (A-frag): lanes 0-7 rows l7 chunk-lo; 8-15 rows +8;
    //   16-23 rows l7 chunk-hi; 24-31 rows +8 chunk-hi
    const uint32_t pBase = smb + ATT_P_OFF + (uint32_t)(wid * PSM_FLOATS * 4)
                         + (uint32_t)((l7 + 8 * lh) * (P_STRIDE * 4) + lq * 16);
    float* Pw = asm_ + (ATT_P_OFF / 4) + wid * PSM_FLOATS;

    // ---- load Q fragments (rna tf32, scale folded) ----
    uint32_t qa[8][4];
    {
        const float* Qr = Qb + (size_t)(q0 + wid * 16) * DHEAD;
        #pragma unroll
        for (int c = 0; c < 8; c++) {
            qa[c][0] = __float_as_uint(f2tf32(0.125f * __ldg(&Qr[(size_t)g * 64 + 8 * c + t4])));
            qa[c][1] = __float_as_uint(f2tf32(0.125f * __ldg(&Qr[(size_t)(g + 8) * 64 + 8 * c + t4])));
            qa[c][2] = __float_as_uint(f2tf32(0.125f * __ldg(&Qr[(size_t)g * 64 + 8 * c + t4 + 4])));
            qa[c][3] = __float_as_uint(f2tf32(0.125f * __ldg(&Qr[(size_t)(g + 8) * 64 + 8 * c + t4 + 4])));
        }
    }

    float o[8][4];
    #pragma unroll
    for (int j = 0; j < 8; j++)
        #pragma unroll
        for (int r = 0; r < 4; r++) o[j][r] = 0.f;
    float m0 = -1e30f, m1 = -1e30f, l0 = 0.f, l1 = 0.f;

    auto stage = [&](int kt, int bufi) {
        uint32_t kd = smb + bufi * (KB_BYTES + VB_BYTES);
        uint32_t vd = kd + KB_BYTES;
        #pragma unroll
        for (int i = 0; i < 8; i++) {
            int j = tid + 128 * i;
            int row = j >> 4, c4 = j & 15;
            cp16(kd + (uint32_t)(row * K_STRIDE + c4 * 4) * 4,
                 Kb + (size_t)(kt * ATT_KT + row) * DHEAD + c4 * 4);
            cp16(vd + (uint32_t)(row * V_STRIDE + c4 * 4) * 4,
                 Vb + (size_t)(kt * ATT_KT + row) * DHEAD + c4 * 4);
        }
    };

    stage(0, 0);
    CP_COMMIT();

    const int NT = SEQ / ATT_KT;   // 32
    for (int kt = 0; kt < NT; kt++) {
        if (kt + 1 < NT) {
            stage(kt + 1, (kt + 1) & 1);
            CP_COMMIT();
            CP_WAIT(1);
        } else {
            CP_WAIT(0);
        }
        __syncthreads();

        const uint32_t kBuf = smb + (kt & 1) * (KB_BYTES + VB_BYTES) + kLane;
        const float* Vsp = asm_ + ((kt & 1) * (KB_BYTES + VB_BYTES) + KB_BYTES) / 4;

        // ---- S = Q @ K^T (K frags via ldmatrix) ----
        float sj[8][4];
        #pragma unroll
        for (int j = 0; j < 8; j++)
            sj[j][0] = sj[j][1] = sj[j][2] = sj[j][3] = 0.f;
        #pragma unroll
        for (int c = 0; c < 8; c++) {
            #pragma unroll
            for (int j2 = 0; j2 < 4; j2++) {
                uint32_t bf4[4];
                ldsm_x4(bf4, kBuf + (uint32_t)(j2 * 16 * K_STRIDE * 4 + c * 32));
                mma_tf32(sj[2 * j2],     qa[c], bf4 + 0);
                mma_tf32(sj[2 * j2 + 1], qa[c], bf4 + 2);
            }
        }

        // ---- online softmax ----
        float mt0 = -1e30f, mt1 = -1e30f;
        #pragma unroll
        for (int j = 0; j < 8; j++) {
            mt0 = fmaxf(mt0, fmaxf(sj[j][0], sj[j][1]));
            mt1 = fmaxf(mt1, fmaxf(sj[j][2], sj[j][3]));
        }
        mt0 = fmaxf(mt0, __shfl_xor_sync(0xffffffffu, mt0, 1));
        mt0 = fmaxf(mt0, __shfl_xor_sync(0xffffffffu, mt0, 2));
        mt1 = fmaxf(mt1, __shfl_xor_sync(0xffffffffu, mt1, 1));
        mt1 = fmaxf(mt1, __shfl_xor_sync(0xffffffffu, mt1, 2));

        float mn0 = fmaxf(m0, mt0), mn1 = fmaxf(m1, mt1);
        float a0 = __expf(m0 - mn0), a1 = __expf(m1 - mn1);
        m0 = mn0; m1 = mn1;

        float rs0 = 0.f, rs1 = 0.f;
        #pragma unroll
        for (int j = 0; j < 8; j++) {
            sj[j][0] = __expf(sj[j][0] - mn0);
            sj[j][1] = __expf(sj[j][1] - mn0);
            sj[j][2] = __expf(sj[j][2] - mn1);
            sj[j][3] = __expf(sj[j][3] - mn1);
            rs0 += sj[j][0] + sj[j][1];
            rs1 += sj[j][2] + sj[j][3];
        }
        rs0 += __shfl_xor_sync(0xffffffffu, rs0, 1);
        rs0 += __shfl_xor_sync(0xffffffffu, rs0, 2);
        rs1 += __shfl_xor_sync(0xffffffffu, rs1, 1);
        rs1 += __shfl_xor_sync(0xffffffffu, rs1, 2);
        l0 = l0 * a0 + rs0;
        l1 = l1 * a1 + rs1;

        #pragma unroll
        for (int j = 0; j < 8; j++) {
            o[j][0] *= a0; o[j][1] *= a0;
            o[j][2] *= a1; o[j][3] *= a1;
        }

        // ---- P: D-layout -> A-layout via per-warp smem round-trip ----
        #pragma unroll
        for (int j = 0; j < 8; j++) {
            *(float2*)&Pw[g * P_STRIDE + 8 * j + 2 * t4] =
                make_float2(sj[j][0], sj[j][1]);
            *(float2*)&Pw[(g + 8) * P_STRIDE + 8 * j + 2 * t4] =
                make_float2(sj[j][2], sj[j][3]);
        }
        __syncwarp();
        uint32_t pa[8][4];
        #pragma unroll
        for (int c = 0; c < 8; c++)
            ldsm_x4(pa[c], pBase + (uint32_t)(c * 32));

        // ---- O += P @ V (V frags scalar, conflict-free) ----
        #pragma unroll
        for (int j = 0; j < 8; j++) {
            #pragma unroll
            for (int c = 0; c < 8; c++) {
                uint32_t bf[2];
                const float* vr = Vsp + (8 * c + t4) * V_STRIDE + 8 * j + g;
                bf[0] = __float_as_uint(vr[0]);
                bf[1] = __float_as_uint(vr[4 * V_STRIDE]);
                mma_tf32(o[j], pa[c], bf);
            }
        }

        __syncthreads();
    }

    // ---- epilogue: tf32-rounded ctx (feeds cp.async out-projection) ----
    float inv0 = 1.f / l0, inv1 = 1.f / l1;
    size_t row0 = (size_t)(b * SEQ + q0 + wid * 16 + g);
    float* dst0 = g_ctx + row0 * D_MODEL + h * DHEAD;
    float* dst1 = dst0 + 8 * D_MODEL;
    #pragma unroll
    for (int j = 0; j < 8; j++) {
        *(float2*)(dst0 + 8 * j + 2 * t4) =
            make_float2(f2tf32(o[j][0] * inv0), f2tf32(o[j][1] * inv0));
        *(float2*)(dst1 + 8 * j + 2 * t4) =
            make_float2(f2tf32(o[j][2] * inv1), f2tf32(o[j][3] * inv1));
    }
}

// ---------------------------------------------------------------------------

extern "C" void kernel_launch(void* const* d_in, const int* in_sizes, int n_in,
                              void* d_out, int out_size)
{
    const float* x     = (const float*)d_in[0];
    const float* w_qkv = (const float*)d_in[1];
    const float* b_qkv = (const float*)d_in[2];
    const float* w_out = (const float*)d_in[3];
    const float* b_out = (const float*)d_in[4];
    float* out = (float*)d_out;

    (void)in_sizes; (void)n_in; (void)out_size;

    cudaFuncSetAttribute(tc_gemm<1>, cudaFuncAttributeMaxDynamicSharedMemorySize, GEMM_SMEM);
    cudaFuncSetAttribute(tc_gemm<0>, cudaFuncAttributeMaxDynamicSharedMemorySize, GEMM_SMEM);
    cudaFuncSetAttribute(attn_mma_kernel, cudaFuncAttributeMaxDynamicSharedMemorySize, ATT_SMEM);

    float* gXt;  cudaGetSymbolAddress((void**)&gXt,  g_Xt);
    float* gWq;  cudaGetSymbolAddress((void**)&gWq,  g_Wq);
    float* gWo;  cudaGetSymbolAddress((void**)&gWo,  g_Wo);
    float* gCtx; cudaGetSymbolAddress((void**)&gCtx, g_ctx);

    // 0) one-shot tf32(rna) pre-rounding of GEMM inputs
    conv_tf32<<<(ROWS * KDIM / 4) / 256, 256>>>(x, gXt);
    conv_tf32<<<(KDIM * QKV_N / 4) / 256, 256>>>(w_qkv, gWq);
    conv_tf32<<<(KDIM * D_MODEL / 4) / 256, 256>>>(w_out, gWo);

    // 1) QKV projection (mma.sync tf32, cp.async feed, LDSM A-frags)
    tc_gemm<1><<<dim3(QKV_N / GBN, ROWS / GBM), 256, GEMM_SMEM>>>(
        gXt, gWq, b_qkv, nullptr, QKV_N);

    // 2) Attention (mma.sync tf32 flash, LDSM K/P frags)
    attn_mma_kernel<<<dim3(SEQ / 64, NHEAD, BATCH), 128, ATT_SMEM>>>();

    // 3) Output projection
    tc_gemm<0><<<dim3(D_MODEL / GBN, ROWS / GBM), 256, GEMM_SMEM>>>(
        gCtx, gWo, b_out, out, D_MODEL);
}

// round 16
// speedup vs baseline: 1.1972x; 1.1972x over previous
#include <cuda_runtime.h>
#include <cstdint>

#define D_MODEL 1024
#define NHEAD   16
#define DHEAD   64
#define BATCH   4
#define SEQ     2048
#define ROWS    (BATCH * SEQ)          // 8192
#define QKV_N   (3 * D_MODEL)          // 3072
#define KDIM    1024

// Scratch (allocation-free rule: __device__ globals)
__device__ float g_Q[BATCH * NHEAD * SEQ * DHEAD];   // [B,H,L,Dh]
__device__ float g_K[BATCH * NHEAD * SEQ * DHEAD];
__device__ float g_V[BATCH * NHEAD * SEQ * DHEAD];
__device__ float g_ctx[ROWS * D_MODEL];              // [B,L,H*Dh] (tf32-rounded)
__device__ float g_Xt[ROWS * KDIM];                  // x, tf32(rna)
__device__ float g_Wq[KDIM * QKV_N];                 // w_qkv, tf32(rna)
__device__ float g_Wo[KDIM * D_MODEL];               // w_out, tf32(rna)

// ---------------------------------------------------------------------------
// helpers
// ---------------------------------------------------------------------------
__device__ __forceinline__ float f2tf32(float x) {
    uint32_t b;
    asm("cvt.rna.tf32.f32 %0, %1;" : "=r"(b) : "f"(x));
    return __uint_as_float(b);
}

// D += A*B, m16n8k8 tf32
__device__ __forceinline__ void mma_tf32(float* d, const uint32_t* a, const uint32_t* b) {
    asm volatile(
        "mma.sync.aligned.m16n8k8.row.col.f32.tf32.tf32.f32 "
        "{%0,%1,%2,%3}, {%4,%5,%6,%7}, {%8,%9}, {%0,%1,%2,%3};"
        : "+f"(d[0]), "+f"(d[1]), "+f"(d[2]), "+f"(d[3])
        : "r"(a[0]), "r"(a[1]), "r"(a[2]), "r"(a[3]), "r"(b[0]), "r"(b[1]));
}

__device__ __forceinline__ uint32_t smem_u32(const void* p) {
    uint32_t a;
    asm("{ .reg .u64 t; cvta.to.shared.u64 t, %1; cvt.u32.u64 %0, t; }"
        : "=r"(a) : "l"(p));
    return a;
}

// ldmatrix x4 (tf32 bits via the b16 path)
__device__ __forceinline__ void ldsm_x4(uint32_t* r, uint32_t addr) {
    asm volatile("ldmatrix.sync.aligned.m8n8.x4.shared.b16 {%0,%1,%2,%3}, [%4];"
                 : "=r"(r[0]), "=r"(r[1]), "=r"(r[2]), "=r"(r[3]) : "r"(addr));
}

__device__ __forceinline__ void cp16(uint32_t dst, const void* src) {
    asm volatile("cp.async.cg.shared.global [%0], [%1], 16;"
                 :: "r"(dst), "l"(src) : "memory");
}
#define CP_COMMIT() asm volatile("cp.async.commit_group;" ::: "memory")
#define CP_WAIT(n)  asm volatile("cp.async.wait_group %0;" :: "n"(n) : "memory")

// ---------------------------------------------------------------------------
// tf32(rna) pre-conversion
// ---------------------------------------------------------------------------
__global__ __launch_bounds__(256) void conv_tf32(
    const float* __restrict__ src, float* __restrict__ dst)
{
    int i = blockIdx.x * 256 + threadIdx.x;
    float4 v = ((const float4*)src)[i];
    v.x = f2tf32(v.x); v.y = f2tf32(v.y);
    v.z = f2tf32(v.z); v.w = f2tf32(v.w);
    ((float4*)dst)[i] = v;
}

// ---------------------------------------------------------------------------
// mma.sync tf32 GEMM: C[M,N] = A[M,1024] @ W[1024,N] + bias
// 2-stage cp.async pipeline (66 KB smem -> 2 CTAs/SM for latency hiding).
// A fragments via ldmatrix.x4 on XOR-swizzled stage; B scalar LDS (padded).
// ---------------------------------------------------------------------------
#define GBM 128
#define GBN 128
#define GBK 32
#define NKIT (KDIM / GBK)        // 32
#define ASTG 4096                // floats: 128*32
#define BSTG 4352                // floats: 32*136
#define STG  (ASTG + BSTG)       // 8448 floats = 33792 B
#define NSTAGE 2
#define GEMM_SMEM (NSTAGE * STG * 4)   // 67584 B -> 2 CTAs/SM

template<int QKV>
__global__ __launch_bounds__(256, 2) void tc_gemm(
    const float* __restrict__ A, const float* __restrict__ W,
    const float* __restrict__ bias, float* __restrict__ out, int ldn)
{
    extern __shared__ float sm[];

    const int tid  = threadIdx.x;
    const int lane = tid & 31;
    const int warp = tid >> 5;
    const int wm   = warp >> 2;     // 0..1
    const int wn   = warp & 3;      // 0..3
    const int g    = lane >> 2;     // 0..7
    const int t4   = lane & 3;      // 0..3
    const int l7   = lane & 7;
    const int lh   = (lane >> 3) & 1;
    const int lq   = lane >> 4;

    const int bn = blockIdx.x * GBN;
    const int bm = blockIdx.y * GBM;

    float d[4][4][4];
    #pragma unroll
    for (int i = 0; i < 4; i++)
        #pragma unroll
        for (int j = 0; j < 4; j++)
            #pragma unroll
            for (int r = 0; r < 4; r++) d[i][j][r] = 0.f;

    const uint32_t smb = smem_u32(sm);

    auto stage = [&](int c, int buf) {
        uint32_t ab = smb + (uint32_t)buf * (STG * 4);
        uint32_t bb = ab + ASTG * 4;
        #pragma unroll
        for (int i = 0; i < 4; i++) {
            int j = tid + 256 * i;
            int m = j >> 3, kc4 = j & 7;
            cp16(ab + (uint32_t)(m * 32 + ((kc4 ^ (m & 7)) << 2)) * 4,
                 A + (size_t)(bm + m) * KDIM + c * GBK + kc4 * 4);
        }
        #pragma unroll
        for (int i = 0; i < 4; i++) {
            int j = tid + 256 * i;
            int k = j >> 5, nc4 = j & 31;
            cp16(bb + (uint32_t)(k * 136 + nc4 * 4) * 4,
                 W + (size_t)(c * GBK + k) * ldn + bn + nc4 * 4);
        }
    };

    stage(0, 0); CP_COMMIT();
    stage(1, 1); CP_COMMIT();

    // A ldsm: addr(tm,tk) = Abuf + (wm*64+tm*16+l7+8lh)*128 + 16*((2tk+lq)^l7)
    const uint32_t aRowOff = (uint32_t)((wm * 64 + l7 + 8 * lh) * 128);

    int buf = 0;
    for (int c = 0; c < NKIT; c++) {
        CP_WAIT(1);
        __syncthreads();

        const uint32_t AbA = smb + (uint32_t)buf * (STG * 4) + aRowOff;
        const float* Bb = sm + buf * STG + ASTG;

        #pragma unroll
        for (int tk = 0; tk < 4; tk++) {
            uint32_t af[4][4], bf[4][2];
            const uint32_t xorv = (uint32_t)(((2 * tk + lq) ^ l7) << 4);
            #pragma unroll
            for (int tm = 0; tm < 4; tm++)
                ldsm_x4(af[tm], AbA + (uint32_t)(tm * 16 * 128) + xorv);
            #pragma unroll
            for (int tn = 0; tn < 4; tn++) {
                int n = wn * 32 + tn * 8 + g;
                bf[tn][0] = __float_as_uint(Bb[(8 * tk + t4) * 136 + n]);
                bf[tn][1] = __float_as_uint(Bb[(8 * tk + t4 + 4) * 136 + n]);
            }
            #pragma unroll
            for (int tm = 0; tm < 4; tm++)
                #pragma unroll
                for (int tn = 0; tn < 4; tn++)
                    mma_tf32(d[tm][tn], af[tm], bf[tn]);
        }

        __syncthreads();
        if (c + 2 < NKIT) stage(c + 2, buf);   // overwrite just-consumed buffer
        CP_COMMIT();

        buf ^= 1;
    }

    // ---- epilogue ----
    const int bb2 = bm >> 11;
    #pragma unroll
    for (int tm = 0; tm < 4; tm++) {
        int m0 = bm + wm * 64 + tm * 16 + g;
        #pragma unroll
        for (int tn = 0; tn < 4; tn++) {
            int n0 = bn + wn * 32 + tn * 8 + t4 * 2;
            float bx = __ldg(&bias[n0]);
            float by = __ldg(&bias[n0 + 1]);
            float v0 = d[tm][tn][0] + bx, v1 = d[tm][tn][1] + by;
            float v2 = d[tm][tn][2] + bx, v3 = d[tm][tn][3] + by;
            if (QKV) {
                int s = n0 >> 10, h = (n0 & 1023) >> 6, d0 = n0 & 63;
                int ll = m0 & (SEQ - 1);
                float* base = (s == 0 ? g_Q : (s == 1 ? g_K : g_V))
                              + ((size_t)(bb2 * NHEAD + h) * SEQ) * DHEAD + d0;
                *(float2*)(base + (size_t)ll * DHEAD)       = make_float2(v0, v1);
                *(float2*)(base + (size_t)(ll + 8) * DHEAD) = make_float2(v2, v3);
            } else {
                *(float2*)(out + (size_t)m0 * D_MODEL + n0)       = make_float2(v0, v1);
                *(float2*)(out + (size_t)(m0 + 8) * D_MODEL + n0) = make_float2(v2, v3);
            }
        }
    }
}

// ---------------------------------------------------------------------------
// Tensor-core flash attention (mma.sync tf32).
// 8 warps/CTA (128 q rows) -> same K/V staging serves 2x rows; 2 CTAs/SM
// -> 16 resident warps to hide the QK->softmax->P->PV serial chains.
// K frags via ldmatrix.x4; P via per-warp smem round-trip; V scalar LDS.
// ---------------------------------------------------------------------------
#define ATT_WARPS 8
#define ATT_THREADS (ATT_WARPS * 32)
#define ATT_QROWS 128
#define ATT_KT   64
#define K_STRIDE 68
#define V_STRIDE 72
#define P_STRIDE 76
#define KB_BYTES (64 * K_STRIDE * 4)   // 17408
#define VB_BYTES (64 * V_STRIDE * 4)   // 18432
#define PSM_FLOATS (16 * P_STRIDE)     // 1216 floats per warp
#define ATT_P_OFF (2 * (KB_BYTES + VB_BYTES))              // 71680
#define ATT_SMEM (ATT_P_OFF + ATT_WARPS * PSM_FLOATS * 4)  // 110592

__global__ __launch_bounds__(ATT_THREADS, 2) void attn_mma_kernel()
{
    extern __shared__ float asm_[];

    const int tid  = threadIdx.x;
    const int lane = tid & 31;
    const int wid  = tid >> 5;
    const int g    = lane >> 2;
    const int t4   = lane & 3;
    const int l7   = lane & 7;
    const int lh   = (lane >> 3) & 1;
    const int lq   = lane >> 4;

    const int b  = blockIdx.z;
    const int h  = blockIdx.y;
    const int q0 = blockIdx.x * ATT_QROWS;

    const size_t head_off = ((size_t)(b * NHEAD) + h) * SEQ * DHEAD;
    const float* __restrict__ Qb = g_Q + head_off;
    const float* __restrict__ Kb = g_K + head_off;
    const float* __restrict__ Vb = g_V + head_off;

    const uint32_t smb = smem_u32(asm_);

    const uint32_t kLane = (uint32_t)((8 * lq + l7) * (K_STRIDE * 4) + lh * 16);
    const uint32_t pBase = smb + ATT_P_OFF + (uint32_t)(wid * PSM_FLOATS * 4)
                         + (uint32_t)((l7 + 8 * lh) * (P_STRIDE * 4) + lq * 16);
    float* Pw = asm_ + (ATT_P_OFF / 4) + wid * PSM_FLOATS;

    // ---- load Q fragments (rna tf32, scale folded) ----
    uint32_t qa[8][4];
    {
        const float* Qr = Qb + (size_t)(q0 + wid * 16) * DHEAD;
        #pragma unroll
        for (int c = 0; c < 8; c++) {
            qa[c][0] = __float_as_uint(f2tf32(0.125f * __ldg(&Qr[(size_t)g * 64 + 8 * c + t4])));
            qa[c][1] = __float_as_uint(f2tf32(0.125f * __ldg(&Qr[(size_t)(g + 8) * 64 + 8 * c + t4])));
            qa[c][2] = __float_as_uint(f2tf32(0.125f * __ldg(&Qr[(size_t)g * 64 + 8 * c + t4 + 4])));
            qa[c][3] = __float_as_uint(f2tf32(0.125f * __ldg(&Qr[(size_t)(g + 8) * 64 + 8 * c + t4 + 4])));
        }
    }

    float o[8][4];
    #pragma unroll
    for (int j = 0; j < 8; j++)
        #pragma unroll
        for (int r = 0; r < 4; r++) o[j][r] = 0.f;
    float m0 = -1e30f, m1 = -1e30f, l0 = 0.f, l1 = 0.f;

    auto stage = [&](int kt, int bufi) {
        uint32_t kd = smb + bufi * (KB_BYTES + VB_BYTES);
        uint32_t vd = kd + KB_BYTES;
        #pragma unroll
        for (int i = 0; i < 4; i++) {
            int j = tid + ATT_THREADS * i;
            int row = j >> 4, c4 = j & 15;
            cp16(kd + (uint32_t)(row * K_STRIDE + c4 * 4) * 4,
                 Kb + (size_t)(kt * ATT_KT + row) * DHEAD + c4 * 4);
            cp16(vd + (uint32_t)(row * V_STRIDE + c4 * 4) * 4,
                 Vb + (size_t)(kt * ATT_KT + row) * DHEAD + c4 * 4);
        }
    };

    stage(0, 0);
    CP_COMMIT();

    const int NT = SEQ / ATT_KT;   // 32
    for (int kt = 0; kt < NT; kt++) {
        if (kt + 1 < NT) {
            stage(kt + 1, (kt + 1) & 1);
            CP_COMMIT();
            CP_WAIT(1);
        } else {
            CP_WAIT(0);
        }
        __syncthreads();

        const uint32_t kBuf = smb + (kt & 1) * (KB_BYTES + VB_BYTES) + kLane;
        const float* Vsp = asm_ + ((kt & 1) * (KB_BYTES + VB_BYTES) + KB_BYTES) / 4;

        // ---- S = Q @ K^T (K frags via ldmatrix) ----
        float sj[8][4];
        #pragma unroll
        for (int j = 0; j < 8; j++)
            sj[j][0] = sj[j][1] = sj[j][2] = sj[j][3] = 0.f;
        #pragma unroll
        for (int c = 0; c < 8; c++) {
            #pragma unroll
            for (int j2 = 0; j2 < 4; j2++) {
                uint32_t bf4[4];
                ldsm_x4(bf4, kBuf + (uint32_t)(j2 * 16 * K_STRIDE * 4 + c * 32));
                mma_tf32(sj[2 * j2],     qa[c], bf4 + 0);
                mma_tf32(sj[2 * j2 + 1], qa[c], bf4 + 2);
            }
        }

        // ---- online softmax ----
        float mt0 = -1e30f, mt1 = -1e30f;
        #pragma unroll
        for (int j = 0; j < 8; j++) {
            mt0 = fmaxf(mt0, fmaxf(sj[j][0], sj[j][1]));
            mt1 = fmaxf(mt1, fmaxf(sj[j][2], sj[j][3]));
        }
        mt0 = fmaxf(mt0, __shfl_xor_sync(0xffffffffu, mt0, 1));
        mt0 = fmaxf(mt0, __shfl_xor_sync(0xffffffffu, mt0, 2));
        mt1 = fmaxf(mt1, __shfl_xor_sync(0xffffffffu, mt1, 1));
        mt1 = fmaxf(mt1, __shfl_xor_sync(0xffffffffu, mt1, 2));

        float mn0 = fmaxf(m0, mt0), mn1 = fmaxf(m1, mt1);
        float a0 = __expf(m0 - mn0), a1 = __expf(m1 - mn1);
        m0 = mn0; m1 = mn1;

        float rs0 = 0.f, rs1 = 0.f;
        #pragma unroll
        for (int j = 0; j < 8; j++) {
            sj[j][0] = __expf(sj[j][0] - mn0);
            sj[j][1] = __expf(sj[j][1] - mn0);
            sj[j][2] = __expf(sj[j][2] - mn1);
            sj[j][3] = __expf(sj[j][3] - mn1);
            rs0 += sj[j][0] + sj[j][1];
            rs1 += sj[j][2] + sj[j][3];
        }
        rs0 += __shfl_xor_sync(0xffffffffu, rs0, 1);
        rs0 += __shfl_xor_sync(0xffffffffu, rs0, 2);
        rs1 += __shfl_xor_sync(0xffffffffu, rs1, 1);
        rs1 += __shfl_xor_sync(0xffffffffu, rs1, 2);
        l0 = l0 * a0 + rs0;
        l1 = l1 * a1 + rs1;

        #pragma unroll
        for (int j = 0; j < 8; j++) {
            o[j][0] *= a0; o[j][1] *= a0;
            o[j][2] *= a1; o[j][3] *= a1;
        }

        // ---- P: D-layout -> A-layout via per-warp smem round-trip ----
        #pragma unroll
        for (int j = 0; j < 8; j++) {
            *(float2*)&Pw[g * P_STRIDE + 8 * j + 2 * t4] =
                make_float2(sj[j][0], sj[j][1]);
            *(float2*)&Pw[(g + 8) * P_STRIDE + 8 * j + 2 * t4] =
                make_float2(sj[j][2], sj[j][3]);
        }
        __syncwarp();
        uint32_t pa[8][4];
        #pragma unroll
        for (int c = 0; c < 8; c++)
            ldsm_x4(pa[c], pBase + (uint32_t)(c * 32));

        // ---- O += P @ V (V frags scalar, conflict-free) ----
        #pragma unroll
        for (int j = 0; j < 8; j++) {
            #pragma unroll
            for (int c = 0; c < 8; c++) {
                uint32_t bf[2];
                const float* vr = Vsp + (8 * c + t4) * V_STRIDE + 8 * j + g;
                bf[0] = __float_as_uint(vr[0]);
                bf[1] = __float_as_uint(vr[4 * V_STRIDE]);
                mma_tf32(o[j], pa[c], bf);
            }
        }

        __syncthreads();
    }

    // ---- epilogue: tf32-rounded ctx (feeds cp.async out-projection) ----
    float inv0 = 1.f / l0, inv1 = 1.f / l1;
    size_t row0 = (size_t)(b * SEQ + q0 + wid * 16 + g);
    float* dst0 = g_ctx + row0 * D_MODEL + h * DHEAD;
    float* dst1 = dst0 + 8 * D_MODEL;
    #pragma unroll
    for (int j = 0; j < 8; j++) {
        *(float2*)(dst0 + 8 * j + 2 * t4) =
            make_float2(f2tf32(o[j][0] * inv0), f2tf32(o[j][1] * inv0));
        *(float2*)(dst1 + 8 * j + 2 * t4) =
            make_float2(f2tf32(o[j][2] * inv1), f2tf32(o[j][3] * inv1));
    }
}

// ---------------------------------------------------------------------------

extern "C" void kernel_launch(void* const* d_in, const int* in_sizes, int n_in,
                              void* d_out, int out_size)
{
    const float* x     = (const float*)d_in[0];
    const float* w_qkv = (const float*)d_in[1];
    const float* b_qkv = (const float*)d_in[2];
    const float* w_out = (const float*)d_in[3];
    const float* b_out = (const float*)d_in[4];
    float* out = (float*)d_out;

    (void)in_sizes; (void)n_in; (void)out_size;

    cudaFuncSetAttribute(tc_gemm<1>, cudaFuncAttributeMaxDynamicSharedMemorySize, GEMM_SMEM);
    cudaFuncSetAttribute(tc_gemm<0>, cudaFuncAttributeMaxDynamicSharedMemorySize, GEMM_SMEM);
    cudaFuncSetAttribute(attn_mma_kernel, cudaFuncAttributeMaxDynamicSharedMemorySize, ATT_SMEM);

    float* gXt;  cudaGetSymbolAddress((void**)&gXt,  g_Xt);
    float* gWq;  cudaGetSymbolAddress((void**)&gWq,  g_Wq);
    float* gWo;  cudaGetSymbolAddress((void**)&gWo,  g_Wo);
    float* gCtx; cudaGetSymbolAddress((void**)&gCtx, g_ctx);

    // 0) one-shot tf32(rna) pre-rounding of GEMM inputs
    conv_tf32<<<(ROWS * KDIM / 4) / 256, 256>>>(x, gXt);
    conv_tf32<<<(KDIM * QKV_N / 4) / 256, 256>>>(w_qkv, gWq);
    conv_tf32<<<(KDIM * D_MODEL / 4) / 256, 256>>>(w_out, gWo);

    // 1) QKV projection (2-stage pipeline, 2 CTAs/SM)
    tc_gemm<1><<<dim3(QKV_N / GBN, ROWS / GBM), 256, GEMM_SMEM>>>(
        gXt, gWq, b_qkv, nullptr, QKV_N);

    // 2) Attention (8 warps/CTA, 2 CTAs/SM)
    attn_mma_kernel<<<dim3(SEQ / ATT_QROWS, NHEAD, BATCH), ATT_THREADS, ATT_SMEM>>>();

    // 3) Output projection
    tc_gemm<0><<<dim3(D_MODEL / GBN, ROWS / GBM), 256, GEMM_SMEM>>>(
        gCtx, gWo, b_out, out, D_MODEL);
}

// round 17
// speedup vs baseline: 1.2635x; 1.0554x over previous
#include <cuda_runtime.h>
#include <cstdint>

#define D_MODEL 1024
#define NHEAD   16
#define DHEAD   64
#define BATCH   4
#define SEQ     2048
#define ROWS    (BATCH * SEQ)          // 8192
#define QKV_N   (3 * D_MODEL)          // 3072
#define KDIM    1024

// Scratch (allocation-free rule: __device__ globals)
__device__ float g_Q[BATCH * NHEAD * SEQ * DHEAD];   // [B,H,L,Dh]
__device__ float g_K[BATCH * NHEAD * SEQ * DHEAD];   // [B,H,L,Dh]
__device__ float g_V[BATCH * NHEAD * SEQ * DHEAD];   // [B,H,Dh,L]  (TRANSPOSED)
__device__ float g_ctx[ROWS * D_MODEL];              // [B,L,H*Dh] (tf32-rounded)
__device__ float g_Xt[ROWS * KDIM];                  // x, tf32(rna)
__device__ float g_Wq[KDIM * QKV_N];                 // w_qkv^T [N][K], tf32(rna)
__device__ float g_Wo[KDIM * D_MODEL];               // w_out^T [N][K], tf32(rna)

// ---------------------------------------------------------------------------
// helpers
// ---------------------------------------------------------------------------
__device__ __forceinline__ float f2tf32(float x) {
    uint32_t b;
    asm("cvt.rna.tf32.f32 %0, %1;" : "=r"(b) : "f"(x));
    return __uint_as_float(b);
}

__device__ __forceinline__ float ex2f(float x) {
    float y;
    asm("ex2.approx.f32 %0, %1;" : "=f"(y) : "f"(x));
    return y;
}

// D += A*B, m16n8k8 tf32
__device__ __forceinline__ void mma_tf32(float* d, const uint32_t* a, const uint32_t* b) {
    asm volatile(
        "mma.sync.aligned.m16n8k8.row.col.f32.tf32.tf32.f32 "
        "{%0,%1,%2,%3}, {%4,%5,%6,%7}, {%8,%9}, {%0,%1,%2,%3};"
        : "+f"(d[0]), "+f"(d[1]), "+f"(d[2]), "+f"(d[3])
        : "r"(a[0]), "r"(a[1]), "r"(a[2]), "r"(a[3]), "r"(b[0]), "r"(b[1]));
}

__device__ __forceinline__ uint32_t smem_u32(const void* p) {
    uint32_t a;
    asm("{ .reg .u64 t; cvta.to.shared.u64 t, %1; cvt.u32.u64 %0, t; }"
        : "=r"(a) : "l"(p));
    return a;
}

// ldmatrix x4 (tf32 bits via the b16 path):
// lane L of tile t gets 4B element L%4 of the 16B row addressed by lane 8t+L/4
__device__ __forceinline__ void ldsm_x4(uint32_t* r, uint32_t addr) {
    asm volatile("ldmatrix.sync.aligned.m8n8.x4.shared.b16 {%0,%1,%2,%3}, [%4];"
                 : "=r"(r[0]), "=r"(r[1]), "=r"(r[2]), "=r"(r[3]) : "r"(addr));
}

__device__ __forceinline__ void cp16(uint32_t dst, const void* src) {
    asm volatile("cp.async.cg.shared.global [%0], [%1], 16;"
                 :: "r"(dst), "l"(src) : "memory");
}
#define CP_COMMIT() asm volatile("cp.async.commit_group;" ::: "memory")
#define CP_WAIT(n)  asm volatile("cp.async.wait_group %0;" :: "n"(n) : "memory")

// ---------------------------------------------------------------------------
// one-shot input prep: plain tf32 round (x), tiled transpose+tf32 (weights)
// ---------------------------------------------------------------------------
__global__ __launch_bounds__(256) void conv_tf32(
    const float* __restrict__ src, float* __restrict__ dst)
{
    int i = blockIdx.x * 256 + threadIdx.x;
    float4 v = ((const float4*)src)[i];
    v.x = f2tf32(v.x); v.y = f2tf32(v.y);
    v.z = f2tf32(v.z); v.w = f2tf32(v.w);
    ((float4*)dst)[i] = v;
}

// dst[n][k] = tf32(src[k][n]); src is rows x cols = K x N
__global__ __launch_bounds__(256) void transpose_tf32(
    const float* __restrict__ src, float* __restrict__ dst, int cols /*N*/, int rows /*K*/)
{
    __shared__ float t[32][33];
    const int tx = threadIdx.x & 31, ty = threadIdx.x >> 5;   // 32x8
    const int bx = blockIdx.x * 32;  // col (n)
    const int by = blockIdx.y * 32;  // row (k)
    #pragma unroll
    for (int i = 0; i < 4; i++)
        t[ty + 8 * i][tx] = src[(size_t)(by + ty + 8 * i) * cols + bx + tx];
    __syncthreads();
    #pragma unroll
    for (int i = 0; i < 4; i++)
        dst[(size_t)(bx + ty + 8 * i) * rows + by + tx] = f2tf32(t[tx][ty + 8 * i]);
}

// ---------------------------------------------------------------------------
// mma.sync tf32 GEMM: C[M,N] = A[M,1024] @ W[1024,N] + bias,  W given as W^T[N][K]
// 2-stage cp.async pipeline, 64 KB smem. A and B both [rows][32k] XOR-swizzled;
// all fragments via ldmatrix.x4.
// ---------------------------------------------------------------------------
#define GBM 128
#define GBN 128
#define GBK 32
#define NKIT (KDIM / GBK)        // 32
#define ASTG 4096                // floats: 128*32
#define BSTG 4096                // floats: 128*32
#define STG  (ASTG + BSTG)       // 8192 floats = 32768 B
#define NSTAGE 2
#define GEMM_SMEM (NSTAGE * STG * 4)   // 65536 B

template<int QKV>
__global__ __launch_bounds__(256, 2) void tc_gemm(
    const float* __restrict__ A, const float* __restrict__ Wt,
    const float* __restrict__ bias, float* __restrict__ out)
{
    extern __shared__ float sm[];

    const int tid  = threadIdx.x;
    const int lane = tid & 31;
    const int warp = tid >> 5;
    const int wm   = warp >> 2;     // 0..1
    const int wn   = warp & 3;      // 0..3
    const int g    = lane >> 2;     // 0..7
    const int t4   = lane & 3;      // 0..3
    const int l7   = lane & 7;
    const int lh   = (lane >> 3) & 1;
    const int lq   = lane >> 4;

    const int bn = blockIdx.x * GBN;
    const int bm = blockIdx.y * GBM;

    float d[4][4][4];
    #pragma unroll
    for (int i = 0; i < 4; i++)
        #pragma unroll
        for (int j = 0; j < 4; j++)
            #pragma unroll
            for (int r = 0; r < 4; r++) d[i][j][r] = 0.f;

    const uint32_t smb = smem_u32(sm);

    auto stage = [&](int c, int buf) {
        uint32_t ab = smb + (uint32_t)buf * (STG * 4);
        uint32_t bb = ab + ASTG * 4;
        #pragma unroll
        for (int i = 0; i < 4; i++) {
            int j = tid + 256 * i;
            int m = j >> 3, kc4 = j & 7;
            cp16(ab + (uint32_t)(m * 32 + ((kc4 ^ (m & 7)) << 2)) * 4,
                 A + (size_t)(bm + m) * KDIM + c * GBK + kc4 * 4);
        }
        #pragma unroll
        for (int i = 0; i < 4; i++) {
            int j = tid + 256 * i;
            int n = j >> 3, kc4 = j & 7;
            cp16(bb + (uint32_t)(n * 32 + ((kc4 ^ (n & 7)) << 2)) * 4,
                 Wt + (size_t)(bn + n) * KDIM + c * GBK + kc4 * 4);
        }
    };

    stage(0, 0); CP_COMMIT();
    stage(1, 1); CP_COMMIT();

    // A ldsm: addr = Abuf + (wm*64+tm*16+l7+8lh)*128 + 16*((2tk+lq)^l7)
    const uint32_t aRowOff = (uint32_t)((wm * 64 + l7 + 8 * lh) * 128);
    // B ldsm: addr = Bbuf + (wn*32+tn2*16+l7+8lq)*128 + 16*((2tk+lh)^l7)
    const uint32_t bRowOff = (uint32_t)((wn * 32 + l7 + 8 * lq) * 128);

    int buf = 0;
    for (int c = 0; c < NKIT; c++) {
        CP_WAIT(1);
        __syncthreads();

        const uint32_t AbA = smb + (uint32_t)buf * (STG * 4) + aRowOff;
        const uint32_t BbB = smb + (uint32_t)buf * (STG * 4) + ASTG * 4 + bRowOff;

        #pragma unroll
        for (int tk = 0; tk < 4; tk++) {
            uint32_t af[4][4], bf[4][2];
            const uint32_t axor = (uint32_t)(((2 * tk + lq) ^ l7) << 4);
            const uint32_t bxor = (uint32_t)(((2 * tk + lh) ^ l7) << 4);
            #pragma unroll
            for (int tm = 0; tm < 4; tm++)
                ldsm_x4(af[tm], AbA + (uint32_t)(tm * 16 * 128) + axor);
            #pragma unroll
            for (int tn2 = 0; tn2 < 2; tn2++) {
                uint32_t bf4[4];
                ldsm_x4(bf4, BbB + (uint32_t)(tn2 * 16 * 128) + bxor);
                bf[2 * tn2][0]     = bf4[0]; bf[2 * tn2][1]     = bf4[1];
                bf[2 * tn2 + 1][0] = bf4[2]; bf[2 * tn2 + 1][1] = bf4[3];
            }
            #pragma unroll
            for (int tm = 0; tm < 4; tm++)
                #pragma unroll
                for (int tn = 0; tn < 4; tn++)
                    mma_tf32(d[tm][tn], af[tm], bf[tn]);
        }

        __syncthreads();
        if (c + 2 < NKIT) stage(c + 2, buf);
        CP_COMMIT();

        buf ^= 1;
    }

    // ---- epilogue ----
    const int bb2 = bm >> 11;
    #pragma unroll
    for (int tm = 0; tm < 4; tm++) {
        int m0 = bm + wm * 64 + tm * 16 + g;
        #pragma unroll
        for (int tn = 0; tn < 4; tn++) {
            int n0 = bn + wn * 32 + tn * 8 + t4 * 2;
            float bx = __ldg(&bias[n0]);
            float by = __ldg(&bias[n0 + 1]);
            float v0 = d[tm][tn][0] + bx, v1 = d[tm][tn][1] + by;
            float v2 = d[tm][tn][2] + bx, v3 = d[tm][tn][3] + by;
            if (QKV) {
                int s = n0 >> 10, h = (n0 & 1023) >> 6, d0 = n0 & 63;
                int ll = m0 & (SEQ - 1);
                if (s == 2) {
                    // V transposed: g_V[b][h][d][seq]
                    float* base = g_V + ((size_t)(bb2 * NHEAD + h) * DHEAD + d0) * SEQ;
                    base[ll]           = v0;
                    base[SEQ + ll]     = v1;
                    base[ll + 8]       = v2;
                    base[SEQ + ll + 8] = v3;
                } else {
                    float* base = (s == 0 ? g_Q : g_K)
                                  + ((size_t)(bb2 * NHEAD + h) * SEQ) * DHEAD + d0;
                    *(float2*)(base + (size_t)ll * DHEAD)       = make_float2(v0, v1);
                    *(float2*)(base + (size_t)(ll + 8) * DHEAD) = make_float2(v2, v3);
                }
            } else {
                *(float2*)(out + (size_t)m0 * D_MODEL + n0)       = make_float2(v0, v1);
                *(float2*)(out + (size_t)(m0 + 8) * D_MODEL + n0) = make_float2(v2, v3);
            }
        }
    }
}

// ---------------------------------------------------------------------------
// Tensor-core flash attention (mma.sync tf32).
// K [key][d] and V^T [d][key] both staged stride-68; K and V fragments via
// ldmatrix.x4. Softmax in exp2 domain. P via per-warp smem round-trip.
// ---------------------------------------------------------------------------
#define ATT_WARPS 8
#define ATT_THREADS (ATT_WARPS * 32)
#define ATT_QROWS 128
#define ATT_KT   64
#define KV_STRIDE 68
#define P_STRIDE 76
#define KB_BYTES (64 * KV_STRIDE * 4)   // 17408
#define VB_BYTES (64 * KV_STRIDE * 4)   // 17408
#define PSM_FLOATS (16 * P_STRIDE)      // 1216 floats per warp
#define ATT_P_OFF (2 * (KB_BYTES + VB_BYTES))              // 69632
#define ATT_SMEM (ATT_P_OFF + ATT_WARPS * PSM_FLOATS * 4)  // 108544

__global__ __launch_bounds__(ATT_THREADS, 2) void attn_mma_kernel()
{
    extern __shared__ float asm_[];

    const int tid  = threadIdx.x;
    const int lane = tid & 31;
    const int wid  = tid >> 5;
    const int g    = lane >> 2;
    const int t4   = lane & 3;
    const int l7   = lane & 7;
    const int lh   = (lane >> 3) & 1;
    const int lq   = lane >> 4;

    const int b  = blockIdx.z;
    const int h  = blockIdx.y;
    const int q0 = blockIdx.x * ATT_QROWS;

    const float* __restrict__ Qb = g_Q + ((size_t)(b * NHEAD) + h) * SEQ * DHEAD;
    const float* __restrict__ Kb = g_K + ((size_t)(b * NHEAD) + h) * SEQ * DHEAD;
    const float* __restrict__ Vb = g_V + ((size_t)(b * NHEAD) + h) * DHEAD * SEQ; // V^T

    const uint32_t smb = smem_u32(asm_);

    const uint32_t kvLane = (uint32_t)((8 * lq + l7) * (KV_STRIDE * 4) + lh * 16);
    const uint32_t pBase = smb + ATT_P_OFF + (uint32_t)(wid * PSM_FLOATS * 4)
                         + (uint32_t)((l7 + 8 * lh) * (P_STRIDE * 4) + lq * 16);
    float* Pw = asm_ + (ATT_P_OFF / 4) + wid * PSM_FLOATS;

    // ---- load Q fragments (rna tf32, scale*log2e folded -> exp2 softmax) ----
    const float QSC = 0.125f * 1.44269504088896340736f;
    uint32_t qa[8][4];
    {
        const float* Qr = Qb + (size_t)(q0 + wid * 16) * DHEAD;
        #pragma unroll
        for (int c = 0; c < 8; c++) {
            qa[c][0] = __float_as_uint(f2tf32(QSC * __ldg(&Qr[(size_t)g * 64 + 8 * c + t4])));
            qa[c][1] = __float_as_uint(f2tf32(QSC * __ldg(&Qr[(size_t)(g + 8) * 64 + 8 * c + t4])));
            qa[c][2] = __float_as_uint(f2tf32(QSC * __ldg(&Qr[(size_t)g * 64 + 8 * c + t4 + 4])));
            qa[c][3] = __float_as_uint(f2tf32(QSC * __ldg(&Qr[(size_t)(g + 8) * 64 + 8 * c + t4 + 4])));
        }
    }

    float o[8][4];
    #pragma unroll
    for (int j = 0; j < 8; j++)
        #pragma unroll
        for (int r = 0; r < 4; r++) o[j][r] = 0.f;
    float m0 = -1e30f, m1 = -1e30f, l0 = 0.f, l1 = 0.f;

    auto stage = [&](int kt, int bufi) {
        uint32_t kd = smb + bufi * (KB_BYTES + VB_BYTES);
        uint32_t vd = kd + KB_BYTES;
        #pragma unroll
        for (int i = 0; i < 4; i++) {
            int j = tid + ATT_THREADS * i;
            int row = j >> 4, c4 = j & 15;
            // K: row = key, 64 d floats per row
            cp16(kd + (uint32_t)(row * KV_STRIDE + c4 * 4) * 4,
                 Kb + (size_t)(kt * ATT_KT + row) * DHEAD + c4 * 4);
            // V^T: row = d, 64 key floats per row
            cp16(vd + (uint32_t)(row * KV_STRIDE + c4 * 4) * 4,
                 Vb + (size_t)row * SEQ + kt * ATT_KT + c4 * 4);
        }
    };

    stage(0, 0);
    CP_COMMIT();

    const int NT = SEQ / ATT_KT;   // 32
    for (int kt = 0; kt < NT; kt++) {
        if (kt + 1 < NT) {
            stage(kt + 1, (kt + 1) & 1);
            CP_COMMIT();
            CP_WAIT(1);
        } else {
            CP_WAIT(0);
        }
        __syncthreads();

        const uint32_t kBuf = smb + (kt & 1) * (KB_BYTES + VB_BYTES) + kvLane;
        const uint32_t vBuf = kBuf + KB_BYTES;

        // ---- S = Q @ K^T (K frags via ldmatrix) ----
        float sj[8][4];
        #pragma unroll
        for (int j = 0; j < 8; j++)
            sj[j][0] = sj[j][1] = sj[j][2] = sj[j][3] = 0.f;
        #pragma unroll
        for (int c = 0; c < 8; c++) {
            #pragma unroll
            for (int j2 = 0; j2 < 4; j2++) {
                uint32_t bf4[4];
                ldsm_x4(bf4, kBuf + (uint32_t)(j2 * 16 * KV_STRIDE * 4 + c * 32));
                mma_tf32(sj[2 * j2],     qa[c], bf4 + 0);
                mma_tf32(sj[2 * j2 + 1], qa[c], bf4 + 2);
            }
        }

        // ---- online softmax (exp2 domain) ----
        float mt0 = -1e30f, mt1 = -1e30f;
        #pragma unroll
        for (int j = 0; j < 8; j++) {
            mt0 = fmaxf(mt0, fmaxf(sj[j][0], sj[j][1]));
            mt1 = fmaxf(mt1, fmaxf(sj[j][2], sj[j][3]));
        }
        mt0 = fmaxf(mt0, __shfl_xor_sync(0xffffffffu, mt0, 1));
        mt0 = fmaxf(mt0, __shfl_xor_sync(0xffffffffu, mt0, 2));
        mt1 = fmaxf(mt1, __shfl_xor_sync(0xffffffffu, mt1, 1));
        mt1 = fmaxf(mt1, __shfl_xor_sync(0xffffffffu, mt1, 2));

        float mn0 = fmaxf(m0, mt0), mn1 = fmaxf(m1, mt1);
        float a0 = ex2f(m0 - mn0), a1 = ex2f(m1 - mn1);
        m0 = mn0; m1 = mn1;

        float rs0 = 0.f, rs1 = 0.f;
        #pragma unroll
        for (int j = 0; j < 8; j++) {
            sj[j][0] = ex2f(sj[j][0] - mn0);
            sj[j][1] = ex2f(sj[j][1] - mn0);
            sj[j][2] = ex2f(sj[j][2] - mn1);
            sj[j][3] = ex2f(sj[j][3] - mn1);
            rs0 += sj[j][0] + sj[j][1];
            rs1 += sj[j][2] + sj[j][3];
        }
        rs0 += __shfl_xor_sync(0xffffffffu, rs0, 1);
        rs0 += __shfl_xor_sync(0xffffffffu, rs0, 2);
        rs1 += __shfl_xor_sync(0xffffffffu, rs1, 1);
        rs1 += __shfl_xor_sync(0xffffffffu, rs1, 2);
        l0 = l0 * a0 + rs0;
        l1 = l1 * a1 + rs1;

        #pragma unroll
        for (int j = 0; j < 8; j++) {
            o[j][0] *= a0; o[j][1] *= a0;
            o[j][2] *= a1; o[j][3] *= a1;
        }

        // ---- P: D-layout -> A-layout via per-warp smem round-trip ----
        #pragma unroll
        for (int j = 0; j < 8; j++) {
            *(float2*)&Pw[g * P_STRIDE + 8 * j + 2 * t4] =
                make_float2(sj[j][0], sj[j][1]);
            *(float2*)&Pw[(g + 8) * P_STRIDE + 8 * j + 2 * t4] =
                make_float2(sj[j][2], sj[j][3]);
        }
        __syncwarp();
        uint32_t pa[8][4];
        #pragma unroll
        for (int c = 0; c < 8; c++)
            ldsm_x4(pa[c], pBase + (uint32_t)(c * 32));

        // ---- O += P @ V (V frags via ldmatrix on V^T) ----
        #pragma unroll
        for (int c = 0; c < 8; c++) {
            #pragma unroll
            for (int j2 = 0; j2 < 4; j2++) {
                uint32_t bf4[4];
                ldsm_x4(bf4, vBuf + (uint32_t)(j2 * 16 * KV_STRIDE * 4 + c * 32));
                mma_tf32(o[2 * j2],     pa[c], bf4 + 0);
                mma_tf32(o[2 * j2 + 1], pa[c], bf4 + 2);
            }
        }

        __syncthreads();
    }

    // ---- epilogue: tf32-rounded ctx (feeds cp.async out-projection) ----
    float inv0 = 1.f / l0, inv1 = 1.f / l1;
    size_t row0 = (size_t)(b * SEQ + q0 + wid * 16 + g);
    float* dst0 = g_ctx + row0 * D_MODEL + h * DHEAD;
    float* dst1 = dst0 + 8 * D_MODEL;
    #pragma unroll
    for (int j = 0; j < 8; j++) {
        *(float2*)(dst0 + 8 * j + 2 * t4) =
            make_float2(f2tf32(o[j][0] * inv0), f2tf32(o[j][1] * inv0));
        *(float2*)(dst1 + 8 * j + 2 * t4) =
            make_float2(f2tf32(o[j][2] * inv1), f2tf32(o[j][3] * inv1));
    }
}

// ---------------------------------------------------------------------------

extern "C" void kernel_launch(void* const* d_in, const int* in_sizes, int n_in,
                              void* d_out, int out_size)
{
    const float* x     = (const float*)d_in[0];
    const float* w_qkv = (const float*)d_in[1];
    const float* b_qkv = (const float*)d_in[2];
    const float* w_out = (const float*)d_in[3];
    const float* b_out = (const float*)d_in[4];
    float* out = (float*)d_out;

    (void)in_sizes; (void)n_in; (void)out_size;

    cudaFuncSetAttribute(tc_gemm<1>, cudaFuncAttributeMaxDynamicSharedMemorySize, GEMM_SMEM);
    cudaFuncSetAttribute(tc_gemm<0>, cudaFuncAttributeMaxDynamicSharedMemorySize, GEMM_SMEM);
    cudaFuncSetAttribute(attn_mma_kernel, cudaFuncAttributeMaxDynamicSharedMemorySize, ATT_SMEM);

    float* gXt;  cudaGetSymbolAddress((void**)&gXt,  g_Xt);
    float* gWq;  cudaGetSymbolAddress((void**)&gWq,  g_Wq);
    float* gWo;  cudaGetSymbolAddress((void**)&gWo,  g_Wo);
    float* gCtx; cudaGetSymbolAddress((void**)&gCtx, g_ctx);

    // 0) one-shot prep: x -> tf32; weights -> transposed tf32 [N][K]
    conv_tf32<<<(ROWS * KDIM / 4) / 256, 256>>>(x, gXt);
    transpose_tf32<<<dim3(QKV_N / 32, KDIM / 32), 256>>>(w_qkv, gWq, QKV_N, KDIM);
    transpose_tf32<<<dim3(D_MODEL / 32, KDIM / 32), 256>>>(w_out, gWo, D_MODEL, KDIM);

    // 1) QKV projection (all-LDSM fragments) + per-head scatter (V transposed)
    tc_gemm<1><<<dim3(QKV_N / GBN, ROWS / GBM), 256, GEMM_SMEM>>>(
        gXt, gWq, b_qkv, nullptr);

    // 2) Attention (K and V^T fragments via ldmatrix, exp2 softmax)
    attn_mma_kernel<<<dim3(SEQ / ATT_QROWS, NHEAD, BATCH), ATT_THREADS, ATT_SMEM>>>();

    // 3) Output projection
    tc_gemm<0><<<dim3(D_MODEL / GBN, ROWS / GBM), 256, GEMM_SMEM>>>(
        gCtx, gWo, b_out, out);
}